// round 13
// baseline (speedup 1.0000x reference)
#include <cuda_runtime.h>
#include <stdint.h>

#define NVIS 4096
#define NHID 1024
#define TT   64
#define BB   32

#define RM_OFF (NVIS*TT*BB)              /* 8388608  */
#define RT_OFF (RM_OFF + NHID*TT*BB)     /* 10485760 */

// ---------------------------------------------------------------------------
// Scratch (static device globals — no allocation)
// ---------------------------------------------------------------------------
__device__ __align__(16) uint32_t g_vbits[TT * NVIS]; // v bitmasks word[t*NV+k], bit b
__device__ __align__(16) uint32_t g_vmbits[NVIS];     // vm bitmasks
__device__ __align__(16) uint32_t g_h1bits[NHID];     // hid1 samples (vis1 input)
__device__ __align__(16) uint32_t g_h2bits[NHID];     // hid2 samples (vis2 input)
__device__ __align__(16) float    g_rT[NHID * BB];    // r recurrence [h][b]
__device__ __align__(16) float    g_bias2[2][NHID*BB];// bias, double-buffered by t&1

// ---------------------------------------------------------------------------
// Threefry-2x32 (exact; 20 rounds, 5 key injections) — DO NOT MODIFY (passing)
// ---------------------------------------------------------------------------
__host__ __device__ __forceinline__ void tf2x32(uint32_t k0, uint32_t k1,
                                                uint32_t x0, uint32_t x1,
                                                uint32_t& o0, uint32_t& o1) {
    uint32_t ks2 = k0 ^ k1 ^ 0x1BD11BDAu;
    x0 += k0; x1 += k1;
#define TF_R(r) { x0 += x1; x1 = (x1 << (r)) | (x1 >> (32 - (r))); x1 ^= x0; }
    TF_R(13) TF_R(15) TF_R(26) TF_R(6)   x0 += k1;  x1 += ks2 + 1u;
    TF_R(17) TF_R(29) TF_R(16) TF_R(24)  x0 += ks2; x1 += k0  + 2u;
    TF_R(13) TF_R(15) TF_R(26) TF_R(6)   x0 += k0;  x1 += k1  + 3u;
    TF_R(17) TF_R(29) TF_R(16) TF_R(24)  x0 += k1;  x1 += ks2 + 4u;
    TF_R(13) TF_R(15) TF_R(26) TF_R(6)   x0 += ks2; x1 += k0  + 5u;
#undef TF_R
    o0 = x0; o1 = x1;
}

__device__ __forceinline__ float jax_uniform(uint32_t k0, uint32_t k1, uint32_t idx) {
    uint32_t o0, o1;
    tf2x32(k0, k1, 0u, idx, o0, o1);
    uint32_t bits = o0 ^ o1;
    return __uint_as_float((bits >> 9) | 0x3f800000u) - 1.0f;
}

__device__ __forceinline__ float sigmoidf_(float x) {
    return 1.0f / (1.0f + expf(-x));
}

// ---------------------------------------------------------------------------
// Masked adds (bit-identical to fmaf(w, v, acc), v in {0,1})
// ---------------------------------------------------------------------------
__device__ __forceinline__ void madd2(float& a0, float& a1, float w0, float w1,
                                      uint32_t word, uint32_t bb) {
    asm("{\n\t.reg .pred p;\n\t.reg .b32 t;\n\t"
        "and.b32 t, %4, %5;\n\t"
        "setp.ne.u32 p, t, 0;\n\t"
        "@p add.f32 %0, %0, %2;\n\t"
        "@p add.f32 %1, %1, %3;\n\t}"
        : "+f"(a0), "+f"(a1) : "f"(w0), "f"(w1), "r"(word), "r"(bb));
}
__device__ __forceinline__ void madd4(float& a0, float& a1, float& a2, float& a3,
                                      float4 w, uint32_t word, uint32_t bb) {
    asm("{\n\t.reg .pred p;\n\t.reg .b32 t;\n\t"
        "and.b32 t, %8, %9;\n\t"
        "setp.ne.u32 p, t, 0;\n\t"
        "@p add.f32 %0, %0, %4;\n\t"
        "@p add.f32 %1, %1, %5;\n\t"
        "@p add.f32 %2, %2, %6;\n\t"
        "@p add.f32 %3, %3, %7;\n\t}"
        : "+f"(a0), "+f"(a1), "+f"(a2), "+f"(a3)
        : "f"(w.x), "f"(w.y), "f"(w.z), "f"(w.w), "r"(word), "r"(bb));
}

// ---------------------------------------------------------------------------
// cp.async helpers
// ---------------------------------------------------------------------------
__device__ __forceinline__ uint32_t smem_u32(const void* p) {
    return (uint32_t)__cvta_generic_to_shared(p);
}
__device__ __forceinline__ void cp_async16(uint32_t saddr, const void* g) {
    asm volatile("cp.async.ca.shared.global [%0], [%1], 16;\n" :: "r"(saddr), "l"(g));
}
__device__ __forceinline__ void cp_commit() {
    asm volatile("cp.async.commit_group;\n");
}
__device__ __forceinline__ void cp_wait1() {
    asm volatile("cp.async.wait_group 1;\n" ::: "memory");
}
__device__ __forceinline__ void cp_wait0() {
    asm volatile("cp.async.wait_group 0;\n" ::: "memory");
}

// Stage one [8 rows x 512 cols] float tile (16KB) into smem. NT threads.
__device__ __forceinline__ void stage8x512_128(uint32_t sbase, const float* gsrc,
                                               int rowstride, int tid) {
#pragma unroll
    for (int q = 0; q < 8; q++) {
        int cc  = q * 128 + tid;
        int rr  = cc >> 7;
        int c16 = cc & 127;
        cp_async16(sbase + (uint32_t)(rr * 512 + c16 * 4) * 4,
                   gsrc + (size_t)rr * rowstride + c16 * 4);
    }
    cp_commit();
}
__device__ __forceinline__ void stage8x512_256(uint32_t sbase, const float* gsrc,
                                               int rowstride, int tid) {
#pragma unroll
    for (int q = 0; q < 4; q++) {
        int cc  = q * 256 + tid;
        int rr  = cc >> 7;
        int c16 = cc & 127;
        cp_async16(sbase + (uint32_t)(rr * 512 + c16 * 4) * 4,
                   gsrc + (size_t)rr * rowstride + c16 * 4);
    }
    cp_commit();
}

// ---------------------------------------------------------------------------
// Pack v [NV][T][B] -> bitmasks (once per replay)
// ---------------------------------------------------------------------------
__global__ void __launch_bounds__(256) pack_v_kernel(const float* __restrict__ v)
{
    int g    = blockIdx.x * 256 + threadIdx.x;
    int lane = g & 31;
    int w    = g >> 5;
    int k    = w & (NVIS - 1);
    int t    = w >> 12;
    float val = v[(size_t)k * (TT * BB) + t * BB + lane];
    uint32_t m = __ballot_sync(0xffffffffu, val != 0.0f);
    if (lane == 0) g_vbits[t * NVIS + k] = m;
}

// ---------------------------------------------------------------------------
// Args
// ---------------------------------------------------------------------------
struct HidArgs {
    const float*    W;
    const float*    U;
    const uint32_t* vbits;
    const float*    bvec;
    int             phase;     // 0: b_init, 1: U@r + b_h, 2: cached
    const float*    bias_rd;
    float*          bias_wr;
    float*          r_out;
    float*          s_out;
    uint32_t*       hb_out;
    uint32_t        kk0, kk1;
};
struct VisArgs {
    const float*    W;
    const float*    bv;
    const uint32_t* hbits;
    int             mode;      // 0: vm bitmask out, 1: v_model floats out
    uint32_t*       vm_out;
    float*          outp;
    uint32_t        kk0, kk1;
};

// ---------------------------------------------------------------------------
// Single-phase hidden kernel (12.36/7.29ms-build body; 128 blocks x 128 thr)
// ---------------------------------------------------------------------------
__global__ void __launch_bounds__(128) hid_single(HidArgs a)
{
    __shared__ float sW[2][8 * 512];
    const int tid   = threadIdx.x;
    const int wid   = tid >> 5;
    const int b     = tid & 31;
    const int hbase = blockIdx.x * 8;
    const int h0    = hbase + wid * 2;
    const int h1    = h0 + 1;
    const uint32_t bb = 1u << b;
    const uint32_t sm0 = smem_u32(&sW[0][0]);
    const uint32_t sm1 = smem_u32(&sW[1][0]);

    float bias0, bias1;
    if (a.phase == 1) {
        float a0 = 0.f, a1 = 0.f;
        stage8x512_128(sm0, a.U + (size_t)hbase * NHID + 0,   NHID, tid);
        stage8x512_128(sm1, a.U + (size_t)hbase * NHID + 512, NHID, tid);
        for (int kt = 0; kt < 2; kt++) {
            if (kt == 0) cp_wait1(); else cp_wait0();
            __syncthreads();
            const float* w0p = &sW[kt][(wid * 2 + 0) * 512];
            const float* w1p = &sW[kt][(wid * 2 + 1) * 512];
            const float* rp  = g_rT + (size_t)(kt * 512) * 32 + b;
#pragma unroll 4
            for (int k = 0; k < 512; k += 4) {
                float4 w0 = *reinterpret_cast<const float4*>(w0p + k);
                float4 w1 = *reinterpret_cast<const float4*>(w1p + k);
                float r0 = rp[(k + 0) * 32];
                float r1 = rp[(k + 1) * 32];
                float r2 = rp[(k + 2) * 32];
                float r3 = rp[(k + 3) * 32];
                a0 = fmaf(w0.x, r0, a0); a1 = fmaf(w1.x, r0, a1);
                a0 = fmaf(w0.y, r1, a0); a1 = fmaf(w1.y, r1, a1);
                a0 = fmaf(w0.z, r2, a0); a1 = fmaf(w1.z, r2, a1);
                a0 = fmaf(w0.w, r3, a0); a1 = fmaf(w1.w, r3, a1);
            }
            __syncthreads();
        }
        bias0 = a0 + a.bvec[h0];
        bias1 = a1 + a.bvec[h1];
        a.bias_wr[h0 * 32 + b] = bias0;
        a.bias_wr[h1 * 32 + b] = bias1;
    } else if (a.phase == 0) {
        bias0 = a.bvec[h0];
        bias1 = a.bvec[h1];
        a.bias_wr[h0 * 32 + b] = bias0;
        a.bias_wr[h1 * 32 + b] = bias1;
    } else {
        bias0 = a.bias_rd[h0 * 32 + b];
        bias1 = a.bias_rd[h1 * 32 + b];
    }

    float a0 = 0.f, a1 = 0.f;
    stage8x512_128(sm0, a.W + (size_t)hbase * NVIS + 0,   NVIS, tid);
    stage8x512_128(sm1, a.W + (size_t)hbase * NVIS + 512, NVIS, tid);
    for (int kt = 0; kt < 8; kt++) {
        if (kt < 7) cp_wait1(); else cp_wait0();
        __syncthreads();
        const float* w0p = &sW[kt & 1][(wid * 2 + 0) * 512];
        const float* w1p = &sW[kt & 1][(wid * 2 + 1) * 512];
        const uint32_t* vb = a.vbits + kt * 512;
#pragma unroll 8
        for (int k = 0; k < 512; k += 4) {
            uint4 vw = *reinterpret_cast<const uint4*>(vb + k);
            float4 w0 = *reinterpret_cast<const float4*>(w0p + k);
            float4 w1 = *reinterpret_cast<const float4*>(w1p + k);
            madd2(a0, a1, w0.x, w1.x, vw.x, bb);
            madd2(a0, a1, w0.y, w1.y, vw.y, bb);
            madd2(a0, a1, w0.z, w1.z, vw.z, bb);
            madd2(a0, a1, w0.w, w1.w, vw.w, bb);
        }
        __syncthreads();
        if (kt + 2 < 8)
            stage8x512_128((kt & 1) ? sm1 : sm0,
                           a.W + (size_t)hbase * NVIS + (kt + 2) * 512, NVIS, tid);
    }

    float r0 = sigmoidf_(a0 + bias0);
    float r1 = sigmoidf_(a1 + bias1);

    if (a.phase != 2) {
        a.r_out[h0 * (TT * BB) + b] = r0;
        a.r_out[h1 * (TT * BB) + b] = r1;
        g_rT[h0 * 32 + b] = r0;
        g_rT[h1 * 32 + b] = r1;
    }
    float u0 = jax_uniform(a.kk0, a.kk1, (uint32_t)(h0 * BB + b));
    float u1 = jax_uniform(a.kk0, a.kk1, (uint32_t)(h1 * BB + b));
    int p0 = (u0 < r0), p1 = (u1 < r1);
    uint32_t m0 = __ballot_sync(0xffffffffu, p0);
    uint32_t m1 = __ballot_sync(0xffffffffu, p1);
    if (b == 0) { a.hb_out[h0] = m0; a.hb_out[h1] = m1; }
    if (a.phase == 2) {
        a.s_out[h0 * (TT * BB) + b] = p0 ? 1.0f : 0.0f;
        a.s_out[h1 * (TT * BB) + b] = p1 ? 1.0f : 0.0f;
    }
}

// ---------------------------------------------------------------------------
// PAIRED hidden kernel: 128 blocks x 256 threads. Warps 0-3 = hid1(t+1)
// (phase 1), warps 4-7 = hid2(t) (phase 2). Both halves compute the SAME
// 8 h-rows of their phase from ONE shared W tile (same rows, different masks).
// All 256 threads stage every tile (uniform cp.async group counts).
// Inner math byte-identical to hid_single.
// ---------------------------------------------------------------------------
__global__ void __launch_bounds__(256) hid_pair(HidArgs A1, HidArgs A2)
{
    __shared__ float sW[2][8 * 512];   // 32KB shared by both halves
    const int tid   = threadIdx.x;
    const int wid   = tid >> 5;        // 0..7
    const int half  = wid >> 2;        // 0 = hid1, 1 = hid2
    const int wloc  = wid & 3;
    const int b     = tid & 31;
    const int hbase = blockIdx.x * 8;
    const int h0    = hbase + wloc * 2;
    const int h1    = h0 + 1;
    const uint32_t bb  = 1u << b;
    const uint32_t sm0 = smem_u32(&sW[0][0]);
    const uint32_t sm1 = smem_u32(&sW[1][0]);

    // ---- U pass: hid1 half computes; everyone stages + barriers ----
    float bias0 = 0.f, bias1 = 0.f;
    float ua0 = 0.f, ua1 = 0.f;
    stage8x512_256(sm0, A1.U + (size_t)hbase * NHID + 0,   NHID, tid);
    stage8x512_256(sm1, A1.U + (size_t)hbase * NHID + 512, NHID, tid);
    for (int kt = 0; kt < 2; kt++) {
        if (kt == 0) cp_wait1(); else cp_wait0();
        __syncthreads();
        if (half == 0) {
            const float* w0p = &sW[kt][(wloc * 2 + 0) * 512];
            const float* w1p = &sW[kt][(wloc * 2 + 1) * 512];
            const float* rp  = g_rT + (size_t)(kt * 512) * 32 + b;
#pragma unroll 4
            for (int k = 0; k < 512; k += 4) {
                float4 w0 = *reinterpret_cast<const float4*>(w0p + k);
                float4 w1 = *reinterpret_cast<const float4*>(w1p + k);
                float r0 = rp[(k + 0) * 32];
                float r1 = rp[(k + 1) * 32];
                float r2 = rp[(k + 2) * 32];
                float r3 = rp[(k + 3) * 32];
                ua0 = fmaf(w0.x, r0, ua0); ua1 = fmaf(w1.x, r0, ua1);
                ua0 = fmaf(w0.y, r1, ua0); ua1 = fmaf(w1.y, r1, ua1);
                ua0 = fmaf(w0.z, r2, ua0); ua1 = fmaf(w1.z, r2, ua1);
                ua0 = fmaf(w0.w, r3, ua0); ua1 = fmaf(w1.w, r3, ua1);
            }
        }
        __syncthreads();
    }
    if (half == 0) {
        bias0 = ua0 + A1.bvec[h0];
        bias1 = ua1 + A1.bvec[h1];
        A1.bias_wr[h0 * 32 + b] = bias0;
        A1.bias_wr[h1 * 32 + b] = bias1;
    } else {
        bias0 = A2.bias_rd[h0 * 32 + b];
        bias1 = A2.bias_rd[h1 * 32 + b];
    }

    // ---- W pass: both halves, shared tiles, per-half masks ----
    const float* Wm = A1.W;   // same W for both phases
    const uint32_t* myvb = (half == 0) ? A1.vbits : A2.vbits;
    float a0 = 0.f, a1 = 0.f;
    stage8x512_256(sm0, Wm + (size_t)hbase * NVIS + 0,   NVIS, tid);
    stage8x512_256(sm1, Wm + (size_t)hbase * NVIS + 512, NVIS, tid);
    for (int kt = 0; kt < 8; kt++) {
        if (kt < 7) cp_wait1(); else cp_wait0();
        __syncthreads();
        const float* w0p = &sW[kt & 1][(wloc * 2 + 0) * 512];
        const float* w1p = &sW[kt & 1][(wloc * 2 + 1) * 512];
        const uint32_t* vb = myvb + kt * 512;
#pragma unroll 8
        for (int k = 0; k < 512; k += 4) {
            uint4 vw = *reinterpret_cast<const uint4*>(vb + k);
            float4 w0 = *reinterpret_cast<const float4*>(w0p + k);
            float4 w1 = *reinterpret_cast<const float4*>(w1p + k);
            madd2(a0, a1, w0.x, w1.x, vw.x, bb);
            madd2(a0, a1, w0.y, w1.y, vw.y, bb);
            madd2(a0, a1, w0.z, w1.z, vw.z, bb);
            madd2(a0, a1, w0.w, w1.w, vw.w, bb);
        }
        __syncthreads();
        if (kt + 2 < 8)
            stage8x512_256((kt & 1) ? sm1 : sm0,
                           Wm + (size_t)hbase * NVIS + (kt + 2) * 512, NVIS, tid);
    }

    float r0 = sigmoidf_(a0 + bias0);
    float r1 = sigmoidf_(a1 + bias1);

    if (half == 0) {
        A1.r_out[h0 * (TT * BB) + b] = r0;
        A1.r_out[h1 * (TT * BB) + b] = r1;
        g_rT[h0 * 32 + b] = r0;
        g_rT[h1 * 32 + b] = r1;
        float u0 = jax_uniform(A1.kk0, A1.kk1, (uint32_t)(h0 * BB + b));
        float u1 = jax_uniform(A1.kk0, A1.kk1, (uint32_t)(h1 * BB + b));
        uint32_t m0 = __ballot_sync(0xffffffffu, u0 < r0);
        uint32_t m1 = __ballot_sync(0xffffffffu, u1 < r1);
        if (b == 0) { A1.hb_out[h0] = m0; A1.hb_out[h1] = m1; }
    } else {
        float u0 = jax_uniform(A2.kk0, A2.kk1, (uint32_t)(h0 * BB + b));
        float u1 = jax_uniform(A2.kk0, A2.kk1, (uint32_t)(h1 * BB + b));
        int p0 = (u0 < r0), p1 = (u1 < r1);
        uint32_t m0 = __ballot_sync(0xffffffffu, p0);
        uint32_t m1 = __ballot_sync(0xffffffffu, p1);
        if (b == 0) { A2.hb_out[h0] = m0; A2.hb_out[h1] = m1; }
        A2.s_out[h0 * (TT * BB) + b] = p0 ? 1.0f : 0.0f;
        A2.s_out[h1 * (TT * BB) + b] = p1 ? 1.0f : 0.0f;
    }
}

// ---------------------------------------------------------------------------
// Single-phase visible kernel (7.29ms-build body; 256 blocks x 128 thr)
// ---------------------------------------------------------------------------
__device__ __forceinline__ void vis_core(int ibase, int wloc, int tid_stage,
                                         int nthr_shift, const VisArgs a, int b,
                                         float* sW0, float* sW1)
{
    // (helper unused; kept minimal — see vis_single / vis_pair bodies)
}

__global__ void __launch_bounds__(128) vis_single(VisArgs a)
{
    __shared__ float sW[2][256 * 16];
    const int tid   = threadIdx.x;
    const int wid   = tid >> 5;
    const int b     = tid & 31;
    const int ibase = blockIdx.x * 16;
    const int i0    = ibase + wid * 4;
    const uint32_t bb = 1u << b;
    const uint32_t sm0 = smem_u32(&sW[0][0]);
    const uint32_t sm1 = smem_u32(&sW[1][0]);

    auto stage = [&](uint32_t sbase, int jt) {
#pragma unroll
        for (int q = 0; q < 8; q++) {
            int cc  = q * 128 + tid;
            int rr  = cc >> 2;
            int c16 = cc & 3;
            cp_async16(sbase + (uint32_t)(rr * 16 + c16 * 4) * 4,
                       a.W + (size_t)(jt * 256 + rr) * NVIS + ibase + c16 * 4);
        }
        cp_commit();
    };

    float a0 = 0.f, a1 = 0.f, a2 = 0.f, a3 = 0.f;
    stage(sm0, 0);
    stage(sm1, 1);
    for (int jt = 0; jt < 4; jt++) {
        if (jt < 3) cp_wait1(); else cp_wait0();
        __syncthreads();
        const float* wp = &sW[jt & 1][wid * 4];
        const uint32_t* hb = a.hbits + jt * 256;
#pragma unroll 4
        for (int j = 0; j < 256; j += 4) {
            uint4 hw = *reinterpret_cast<const uint4*>(hb + j);
            float4 w;
            w = *reinterpret_cast<const float4*>(wp + (j + 0) * 16);
            madd4(a0, a1, a2, a3, w, hw.x, bb);
            w = *reinterpret_cast<const float4*>(wp + (j + 1) * 16);
            madd4(a0, a1, a2, a3, w, hw.y, bb);
            w = *reinterpret_cast<const float4*>(wp + (j + 2) * 16);
            madd4(a0, a1, a2, a3, w, hw.z, bb);
            w = *reinterpret_cast<const float4*>(wp + (j + 3) * 16);
            madd4(a0, a1, a2, a3, w, hw.w, bb);
        }
        __syncthreads();
        if (jt + 2 < 4) stage((jt & 1) ? sm1 : sm0, jt + 2);
    }

    float accs[4] = {a0, a1, a2, a3};
#pragma unroll
    for (int q = 0; q < 4; q++) {
        float r = sigmoidf_(accs[q] + a.bv[i0 + q]);
        float u = jax_uniform(a.kk0, a.kk1, (uint32_t)((i0 + q) * BB + b));
        int pr = (u < r);
        uint32_t m = __ballot_sync(0xffffffffu, pr);
        if (a.mode == 0) {
            if (b == 0) a.vm_out[i0 + q] = m;
        } else {
            a.outp[(size_t)(i0 + q) * (TT * BB) + b] = pr ? 1.0f : 0.0f;
        }
    }
}

// ---------------------------------------------------------------------------
// PAIRED visible kernel: 256 blocks x 256 threads. Warps 0-3 = vis1(t+1),
// warps 4-7 = vis2(t). Both halves cover the same 16 i columns from ONE
// shared W tile; per-half h bitmasks and outputs. Math byte-identical.
// ---------------------------------------------------------------------------
__global__ void __launch_bounds__(256) vis_pair(VisArgs A1, VisArgs A2)
{
    __shared__ float sW[2][256 * 16];
    const int tid   = threadIdx.x;
    const int wid   = tid >> 5;        // 0..7
    const int half  = wid >> 2;
    const int wloc  = wid & 3;
    const int b     = tid & 31;
    const int ibase = blockIdx.x * 16;
    const int i0    = ibase + wloc * 4;
    const uint32_t bb  = 1u << b;
    const uint32_t sm0 = smem_u32(&sW[0][0]);
    const uint32_t sm1 = smem_u32(&sW[1][0]);
    const float* Wm = A1.W;

    auto stage = [&](uint32_t sbase, int jt) {
#pragma unroll
        for (int q = 0; q < 4; q++) {
            int cc  = q * 256 + tid;   // 0..1023
            int rr  = cc >> 2;
            int c16 = cc & 3;
            cp_async16(sbase + (uint32_t)(rr * 16 + c16 * 4) * 4,
                       Wm + (size_t)(jt * 256 + rr) * NVIS + ibase + c16 * 4);
        }
        cp_commit();
    };

    const uint32_t* myhb = (half == 0) ? A1.hbits : A2.hbits;

    float a0 = 0.f, a1 = 0.f, a2 = 0.f, a3 = 0.f;
    stage(sm0, 0);
    stage(sm1, 1);
    for (int jt = 0; jt < 4; jt++) {
        if (jt < 3) cp_wait1(); else cp_wait0();
        __syncthreads();
        const float* wp = &sW[jt & 1][wloc * 4];
        const uint32_t* hb = myhb + jt * 256;
#pragma unroll 4
        for (int j = 0; j < 256; j += 4) {
            uint4 hw = *reinterpret_cast<const uint4*>(hb + j);
            float4 w;
            w = *reinterpret_cast<const float4*>(wp + (j + 0) * 16);
            madd4(a0, a1, a2, a3, w, hw.x, bb);
            w = *reinterpret_cast<const float4*>(wp + (j + 1) * 16);
            madd4(a0, a1, a2, a3, w, hw.y, bb);
            w = *reinterpret_cast<const float4*>(wp + (j + 2) * 16);
            madd4(a0, a1, a2, a3, w, hw.z, bb);
            w = *reinterpret_cast<const float4*>(wp + (j + 3) * 16);
            madd4(a0, a1, a2, a3, w, hw.w, bb);
        }
        __syncthreads();
        if (jt + 2 < 4) stage((jt & 1) ? sm1 : sm0, jt + 2);
    }

    const VisArgs& a = (half == 0) ? A1 : A2;
    float accs[4] = {a0, a1, a2, a3};
#pragma unroll
    for (int q = 0; q < 4; q++) {
        float r = sigmoidf_(accs[q] + a.bv[i0 + q]);
        float u = jax_uniform(a.kk0, a.kk1, (uint32_t)((i0 + q) * BB + b));
        int pr = (u < r);
        uint32_t m = __ballot_sync(0xffffffffu, pr);
        if (a.mode == 0) {
            if (b == 0) a.vm_out[i0 + q] = m;
        } else {
            a.outp[(size_t)(i0 + q) * (TT * BB) + b] = pr ? 1.0f : 0.0f;
        }
    }
}

// ---------------------------------------------------------------------------
// Host: partitionable-threefry key schedule + pipelined launch sequence.
// DAG: hid1(t+1) ⟂ {vis1,hid2,vis2}(t); vis1(t+1) ⟂ vis2(t).
// Paired kernels share W tiles between the two fused phases.
// ---------------------------------------------------------------------------
extern "C" void kernel_launch(void* const* d_in, const int* in_sizes, int n_in,
                              void* d_out, int out_size)
{
    const float* v      = (const float*)d_in[0];   // [NV, T, B]
    const float* W      = (const float*)d_in[1];   // [NH, NV]
    const float* U      = (const float*)d_in[2];   // [NH, NH]
    const float* b_v    = (const float*)d_in[3];
    const float* b_h    = (const float*)d_in[4];
    const float* b_init = (const float*)d_in[5];
    float* out = (float*)d_out;

    uint32_t k0a, k0b, ksa, ksb;
    tf2x32(0u, 42u, 0u, 0u, k0a, k0b);   // k0 (t=0 step key)
    tf2x32(0u, 42u, 0u, 1u, ksa, ksb);   // ks
    static uint32_t sub[TT][4][2];
    for (int t = 0; t < TT; t++) {
        uint32_t sk0, sk1;
        if (t == 0) { sk0 = k0a; sk1 = k0b; }
        else         tf2x32(ksa, ksb, 0u, (uint32_t)(t - 1), sk0, sk1);
        for (int i = 0; i < 4; i++)
            tf2x32(sk0, sk1, 0u, (uint32_t)i, sub[t][i][0], sub[t][i][1]);
    }

    void* p;
    cudaGetSymbolAddress(&p, g_vbits);  uint32_t* pvb  = (uint32_t*)p;
    cudaGetSymbolAddress(&p, g_vmbits); uint32_t* pvmb = (uint32_t*)p;
    cudaGetSymbolAddress(&p, g_h1bits); uint32_t* ph1  = (uint32_t*)p;
    cudaGetSymbolAddress(&p, g_h2bits); uint32_t* ph2  = (uint32_t*)p;
    cudaGetSymbolAddress(&p, g_bias2);  float*    pbias= (float*)p;
    float* bias_buf[2] = { pbias, pbias + NHID * BB };

    pack_v_kernel<<<TT * NVIS * 32 / 256, 256>>>(v);

    auto mk_hid1 = [&](int t) {
        HidArgs a;
        a.W = W; a.U = U;
        a.vbits = pvb + (size_t)t * NVIS;
        a.bvec  = (t == 0) ? b_init : b_h;
        a.phase = (t == 0) ? 0 : 1;
        a.bias_rd = nullptr;
        a.bias_wr = bias_buf[t & 1];
        a.r_out = out + RT_OFF + (size_t)t * BB;
        a.s_out = nullptr;
        a.hb_out = ph1;
        a.kk0 = sub[t][0][0]; a.kk1 = sub[t][0][1];
        return a;
    };
    auto mk_hid2 = [&](int t) {
        HidArgs a;
        a.W = W; a.U = nullptr;
        a.vbits = pvmb;
        a.bvec  = nullptr;
        a.phase = 2;
        a.bias_rd = bias_buf[t & 1];
        a.bias_wr = nullptr;
        a.r_out = nullptr;
        a.s_out = out + RM_OFF + (size_t)t * BB;
        a.hb_out = ph2;
        a.kk0 = sub[t][2][0]; a.kk1 = sub[t][2][1];
        return a;
    };
    auto mk_vis1 = [&](int t) {
        VisArgs a;
        a.W = W; a.bv = b_v; a.hbits = ph1;
        a.mode = 0; a.vm_out = pvmb; a.outp = nullptr;
        a.kk0 = sub[t][1][0]; a.kk1 = sub[t][1][1];
        return a;
    };
    auto mk_vis2 = [&](int t) {
        VisArgs a;
        a.W = W; a.bv = b_v; a.hbits = ph2;
        a.mode = 1; a.vm_out = nullptr; a.outp = out + (size_t)t * BB;
        a.kk0 = sub[t][3][0]; a.kk1 = sub[t][3][1];
        return a;
    };

    // Bootstrap: hid1(0), vis1(0)
    hid_single<<<128, 128>>>(mk_hid1(0));
    vis_single<<<256, 128>>>(mk_vis1(0));

    // Pipelined steady state: shared-tile paired kernels
    for (int t = 0; t < TT - 1; t++) {
        hid_pair<<<128, 256>>>(mk_hid1(t + 1), mk_hid2(t));
        vis_pair<<<256, 256>>>(mk_vis1(t + 1), mk_vis2(t));
    }

    // Tail: hid2(63), vis2(63)
    hid_single<<<128, 128>>>(mk_hid2(TT - 1));
    vis_single<<<256, 128>>>(mk_vis2(TT - 1));
}

// round 14
// speedup vs baseline: 1.5816x; 1.5816x over previous
#include <cuda_runtime.h>
#include <stdint.h>

#define NVIS 4096
#define NHID 1024
#define TT   64
#define BB   32

#define RM_OFF (NVIS*TT*BB)              /* 8388608  */
#define RT_OFF (RM_OFF + NHID*TT*BB)     /* 10485760 */

// ---------------------------------------------------------------------------
// Scratch (static device globals — no allocation)
// ---------------------------------------------------------------------------
__device__ __align__(16) uint32_t g_vbits[TT * NVIS]; // v bitmasks word[t*NV+k], bit b
__device__ __align__(16) uint32_t g_vmbits[NVIS];     // vm bitmasks
__device__ __align__(16) uint32_t g_h1bits[NHID];     // hid1 samples (vis1 input)
__device__ __align__(16) uint32_t g_h2bits[NHID];     // hid2 samples (vis2 input)
__device__ __align__(16) float    g_rT[NHID * BB];    // r recurrence [h][b]
__device__ __align__(16) float    g_bias2[2][NHID*BB];// bias, double-buffered by t&1

// ---------------------------------------------------------------------------
// Threefry-2x32 (exact; 20 rounds, 5 key injections) — DO NOT MODIFY (passing)
// ---------------------------------------------------------------------------
__host__ __device__ __forceinline__ void tf2x32(uint32_t k0, uint32_t k1,
                                                uint32_t x0, uint32_t x1,
                                                uint32_t& o0, uint32_t& o1) {
    uint32_t ks2 = k0 ^ k1 ^ 0x1BD11BDAu;
    x0 += k0; x1 += k1;
#define TF_R(r) { x0 += x1; x1 = (x1 << (r)) | (x1 >> (32 - (r))); x1 ^= x0; }
    TF_R(13) TF_R(15) TF_R(26) TF_R(6)   x0 += k1;  x1 += ks2 + 1u;
    TF_R(17) TF_R(29) TF_R(16) TF_R(24)  x0 += ks2; x1 += k0  + 2u;
    TF_R(13) TF_R(15) TF_R(26) TF_R(6)   x0 += k0;  x1 += k1  + 3u;
    TF_R(17) TF_R(29) TF_R(16) TF_R(24)  x0 += k1;  x1 += ks2 + 4u;
    TF_R(13) TF_R(15) TF_R(26) TF_R(6)   x0 += ks2; x1 += k0  + 5u;
#undef TF_R
    o0 = x0; o1 = x1;
}

__device__ __forceinline__ float jax_uniform(uint32_t k0, uint32_t k1, uint32_t idx) {
    uint32_t o0, o1;
    tf2x32(k0, k1, 0u, idx, o0, o1);
    uint32_t bits = o0 ^ o1;
    return __uint_as_float((bits >> 9) | 0x3f800000u) - 1.0f;
}

__device__ __forceinline__ float sigmoidf_(float x) {
    return 1.0f / (1.0f + expf(-x));
}

// ---------------------------------------------------------------------------
// Masked adds (bit-identical to fmaf(w, v, acc), v in {0,1})
// ---------------------------------------------------------------------------
__device__ __forceinline__ void madd2(float& a0, float& a1, float w0, float w1,
                                      uint32_t word, uint32_t bb) {
    asm("{\n\t.reg .pred p;\n\t.reg .b32 t;\n\t"
        "and.b32 t, %4, %5;\n\t"
        "setp.ne.u32 p, t, 0;\n\t"
        "@p add.f32 %0, %0, %2;\n\t"
        "@p add.f32 %1, %1, %3;\n\t}"
        : "+f"(a0), "+f"(a1) : "f"(w0), "f"(w1), "r"(word), "r"(bb));
}
__device__ __forceinline__ void madd4(float& a0, float& a1, float& a2, float& a3,
                                      float4 w, uint32_t word, uint32_t bb) {
    asm("{\n\t.reg .pred p;\n\t.reg .b32 t;\n\t"
        "and.b32 t, %8, %9;\n\t"
        "setp.ne.u32 p, t, 0;\n\t"
        "@p add.f32 %0, %0, %4;\n\t"
        "@p add.f32 %1, %1, %5;\n\t"
        "@p add.f32 %2, %2, %6;\n\t"
        "@p add.f32 %3, %3, %7;\n\t}"
        : "+f"(a0), "+f"(a1), "+f"(a2), "+f"(a3)
        : "f"(w.x), "f"(w.y), "f"(w.z), "f"(w.w), "r"(word), "r"(bb));
}

// ---------------------------------------------------------------------------
// cp.async helpers
// ---------------------------------------------------------------------------
__device__ __forceinline__ uint32_t smem_u32(const void* p) {
    return (uint32_t)__cvta_generic_to_shared(p);
}
__device__ __forceinline__ void cp_async16(uint32_t saddr, const void* g) {
    asm volatile("cp.async.ca.shared.global [%0], [%1], 16;\n" :: "r"(saddr), "l"(g));
}
__device__ __forceinline__ void cp_commit() {
    asm volatile("cp.async.commit_group;\n");
}
__device__ __forceinline__ void cp_wait1() {
    asm volatile("cp.async.wait_group 1;\n" ::: "memory");
}
__device__ __forceinline__ void cp_wait0() {
    asm volatile("cp.async.wait_group 0;\n" ::: "memory");
}

// Stage one [4 rows x 512 cols] float tile (8KB) into smem. 64 threads.
__device__ __forceinline__ void stage4x512_64(uint32_t sbase, const float* gsrc,
                                              int rowstride, int tid) {
#pragma unroll
    for (int q = 0; q < 8; q++) {
        int cc  = q * 64 + tid;       // 0..511 (16B chunks)
        int rr  = cc >> 7;            // 0..3
        int c16 = cc & 127;
        cp_async16(sbase + (uint32_t)(rr * 512 + c16 * 4) * 4,
                   gsrc + (size_t)rr * rowstride + c16 * 4);
    }
    cp_commit();
}

// ---------------------------------------------------------------------------
// Pack v [NV][T][B] -> bitmasks (once per replay)
// ---------------------------------------------------------------------------
__global__ void __launch_bounds__(256) pack_v_kernel(const float* __restrict__ v)
{
    int g    = blockIdx.x * 256 + threadIdx.x;
    int lane = g & 31;
    int w    = g >> 5;
    int k    = w & (NVIS - 1);
    int t    = w >> 12;
    float val = v[(size_t)k * (TT * BB) + t * BB + lane];
    uint32_t m = __ballot_sync(0xffffffffu, val != 0.0f);
    if (lane == 0) g_vbits[t * NVIS + k] = m;
}

// ---------------------------------------------------------------------------
// Args
// ---------------------------------------------------------------------------
struct HidArgs {
    const float*    W;
    const float*    U;
    const uint32_t* vbits;
    const float*    bvec;
    int             phase;     // 0: b_init, 1: U@r + b_h, 2: cached
    const float*    bias_rd;
    float*          bias_wr;
    float*          r_out;
    float*          s_out;
    uint32_t*       hb_out;
    uint32_t        kk0, kk1;
};
struct VisArgs {
    const float*    W;
    const float*    bv;
    const uint32_t* hbits;
    int             mode;      // 0: vm bitmask out, 1: v_model floats out
    uint32_t*       vm_out;
    float*          outp;
    uint32_t        kk0, kk1;
};

// ---------------------------------------------------------------------------
// Hidden body: SMALL blocks — 64 threads (2 warps), 4 h rows per block.
// blk in [0,256) per phase. Thread = (2 h, b). Tiles 4x512 double-buffered.
// Inner math byte-identical to the 7.29ms build (madd2 chain, same order).
// ---------------------------------------------------------------------------
__device__ __forceinline__ void hid_body(int blk, const HidArgs a)
{
    __shared__ float sW[2][4 * 512];   // 16KB double-buffered tile
    const int tid   = threadIdx.x;     // 0..63
    const int wid   = tid >> 5;        // 0..1
    const int b     = tid & 31;
    const int hbase = blk * 4;
    const int h0    = hbase + wid * 2;
    const int h1    = h0 + 1;
    const uint32_t bb  = 1u << b;
    const uint32_t sm0 = smem_u32(&sW[0][0]);
    const uint32_t sm1 = smem_u32(&sW[1][0]);

    float bias0, bias1;
    if (a.phase == 1) {
        float a0 = 0.f, a1 = 0.f;
        stage4x512_64(sm0, a.U + (size_t)hbase * NHID + 0,   NHID, tid);
        stage4x512_64(sm1, a.U + (size_t)hbase * NHID + 512, NHID, tid);
        for (int kt = 0; kt < 2; kt++) {
            if (kt == 0) cp_wait1(); else cp_wait0();
            __syncthreads();
            const float* w0p = &sW[kt][(wid * 2 + 0) * 512];
            const float* w1p = &sW[kt][(wid * 2 + 1) * 512];
            const float* rp  = g_rT + (size_t)(kt * 512) * 32 + b;
#pragma unroll 4
            for (int k = 0; k < 512; k += 4) {
                float4 w0 = *reinterpret_cast<const float4*>(w0p + k);
                float4 w1 = *reinterpret_cast<const float4*>(w1p + k);
                float r0 = rp[(k + 0) * 32];
                float r1 = rp[(k + 1) * 32];
                float r2 = rp[(k + 2) * 32];
                float r3 = rp[(k + 3) * 32];
                a0 = fmaf(w0.x, r0, a0); a1 = fmaf(w1.x, r0, a1);
                a0 = fmaf(w0.y, r1, a0); a1 = fmaf(w1.y, r1, a1);
                a0 = fmaf(w0.z, r2, a0); a1 = fmaf(w1.z, r2, a1);
                a0 = fmaf(w0.w, r3, a0); a1 = fmaf(w1.w, r3, a1);
            }
            __syncthreads();
        }
        bias0 = a0 + a.bvec[h0];
        bias1 = a1 + a.bvec[h1];
        a.bias_wr[h0 * 32 + b] = bias0;
        a.bias_wr[h1 * 32 + b] = bias1;
    } else if (a.phase == 0) {
        bias0 = a.bvec[h0];
        bias1 = a.bvec[h1];
        a.bias_wr[h0 * 32 + b] = bias0;
        a.bias_wr[h1 * 32 + b] = bias1;
    } else {
        bias0 = a.bias_rd[h0 * 32 + b];
        bias1 = a.bias_rd[h1 * 32 + b];
    }

    float a0 = 0.f, a1 = 0.f;
    stage4x512_64(sm0, a.W + (size_t)hbase * NVIS + 0,   NVIS, tid);
    stage4x512_64(sm1, a.W + (size_t)hbase * NVIS + 512, NVIS, tid);
    for (int kt = 0; kt < 8; kt++) {
        if (kt < 7) cp_wait1(); else cp_wait0();
        __syncthreads();
        const float* w0p = &sW[kt & 1][(wid * 2 + 0) * 512];
        const float* w1p = &sW[kt & 1][(wid * 2 + 1) * 512];
        const uint32_t* vb = a.vbits + kt * 512;
#pragma unroll 8
        for (int k = 0; k < 512; k += 4) {
            uint4 vw = *reinterpret_cast<const uint4*>(vb + k);
            float4 w0 = *reinterpret_cast<const float4*>(w0p + k);
            float4 w1 = *reinterpret_cast<const float4*>(w1p + k);
            madd2(a0, a1, w0.x, w1.x, vw.x, bb);
            madd2(a0, a1, w0.y, w1.y, vw.y, bb);
            madd2(a0, a1, w0.z, w1.z, vw.z, bb);
            madd2(a0, a1, w0.w, w1.w, vw.w, bb);
        }
        __syncthreads();
        // tile kt+2 goes into the buffer just drained: parity kt&1
        if (kt + 2 < 8)
            stage4x512_64((kt & 1) ? sm1 : sm0,
                          a.W + (size_t)hbase * NVIS + (kt + 2) * 512, NVIS, tid);
    }

    float r0 = sigmoidf_(a0 + bias0);
    float r1 = sigmoidf_(a1 + bias1);

    if (a.phase != 2) {
        a.r_out[h0 * (TT * BB) + b] = r0;
        a.r_out[h1 * (TT * BB) + b] = r1;
        g_rT[h0 * 32 + b] = r0;
        g_rT[h1 * 32 + b] = r1;
    }
    float u0 = jax_uniform(a.kk0, a.kk1, (uint32_t)(h0 * BB + b));
    float u1 = jax_uniform(a.kk0, a.kk1, (uint32_t)(h1 * BB + b));
    int p0 = (u0 < r0), p1 = (u1 < r1);
    uint32_t m0 = __ballot_sync(0xffffffffu, p0);
    uint32_t m1 = __ballot_sync(0xffffffffu, p1);
    if (b == 0) { a.hb_out[h0] = m0; a.hb_out[h1] = m1; }
    if (a.phase == 2) {
        a.s_out[h0 * (TT * BB) + b] = p0 ? 1.0f : 0.0f;
        a.s_out[h1 * (TT * BB) + b] = p1 ? 1.0f : 0.0f;
    }
}

__global__ void __launch_bounds__(64) hid_single(HidArgs a)
{
    hid_body(blockIdx.x, a);
}

// Fused: blocks [0,256) = phase A (hid1(t+1)), [256,512) = phase B (hid2(t)).
// Independent blocks — no intra-block lockstep (R13 lesson).
__global__ void __launch_bounds__(64) hid_fused(HidArgs a, HidArgs bgs)
{
    if (blockIdx.x < 256) hid_body(blockIdx.x, a);
    else                  hid_body(blockIdx.x - 256, bgs);
}

// ---------------------------------------------------------------------------
// Visible body (exact 7.29ms-build inner loops). blk in [0,256): 16 i.
// Thread = (4 i, b). mode 0: vm bitmask out; mode 1: v_model floats out.
// ---------------------------------------------------------------------------
__device__ __forceinline__ void vis_body(int blk, const VisArgs a)
{
    __shared__ float sW[2][256 * 16];   // 32KB double-buffered
    const int tid   = threadIdx.x;
    const int wid   = tid >> 5;
    const int b     = tid & 31;
    const int ibase = blk * 16;
    const int i0    = ibase + wid * 4;
    const uint32_t bb = 1u << b;
    const uint32_t sm0 = smem_u32(&sW[0][0]);
    const uint32_t sm1 = smem_u32(&sW[1][0]);

    auto stage = [&](uint32_t sbase, int jt) {
#pragma unroll
        for (int q = 0; q < 8; q++) {
            int cc  = q * 128 + tid;
            int rr  = cc >> 2;
            int c16 = cc & 3;
            cp_async16(sbase + (uint32_t)(rr * 16 + c16 * 4) * 4,
                       a.W + (size_t)(jt * 256 + rr) * NVIS + ibase + c16 * 4);
        }
        cp_commit();
    };

    float a0 = 0.f, a1 = 0.f, a2 = 0.f, a3 = 0.f;
    stage(sm0, 0);
    stage(sm1, 1);
    for (int jt = 0; jt < 4; jt++) {
        if (jt < 3) cp_wait1(); else cp_wait0();
        __syncthreads();
        const float* wp = &sW[jt & 1][wid * 4];
        const uint32_t* hb = a.hbits + jt * 256;
#pragma unroll 4
        for (int j = 0; j < 256; j += 4) {
            uint4 hw = *reinterpret_cast<const uint4*>(hb + j);
            float4 w;
            w = *reinterpret_cast<const float4*>(wp + (j + 0) * 16);
            madd4(a0, a1, a2, a3, w, hw.x, bb);
            w = *reinterpret_cast<const float4*>(wp + (j + 1) * 16);
            madd4(a0, a1, a2, a3, w, hw.y, bb);
            w = *reinterpret_cast<const float4*>(wp + (j + 2) * 16);
            madd4(a0, a1, a2, a3, w, hw.z, bb);
            w = *reinterpret_cast<const float4*>(wp + (j + 3) * 16);
            madd4(a0, a1, a2, a3, w, hw.w, bb);
        }
        __syncthreads();
        if (jt + 2 < 4) stage((jt & 1) ? sm1 : sm0, jt + 2);
    }

    float accs[4] = {a0, a1, a2, a3};
#pragma unroll
    for (int q = 0; q < 4; q++) {
        float r = sigmoidf_(accs[q] + a.bv[i0 + q]);
        float u = jax_uniform(a.kk0, a.kk1, (uint32_t)((i0 + q) * BB + b));
        int pr = (u < r);
        uint32_t m = __ballot_sync(0xffffffffu, pr);
        if (a.mode == 0) {
            if (b == 0) a.vm_out[i0 + q] = m;
        } else {
            a.outp[(size_t)(i0 + q) * (TT * BB) + b] = pr ? 1.0f : 0.0f;
        }
    }
}

__global__ void __launch_bounds__(128) vis_single(VisArgs a)
{
    vis_body(blockIdx.x, a);
}

__global__ void __launch_bounds__(128) vis_fused(VisArgs a, VisArgs bgs)
{
    if (blockIdx.x < 256) vis_body(blockIdx.x, a);
    else                  vis_body(blockIdx.x - 256, bgs);
}

// ---------------------------------------------------------------------------
// Host: partitionable-threefry key schedule + pipelined launch sequence.
// DAG: hid1(t+1) ⟂ {vis1,hid2,vis2}(t); vis1(t+1) ⟂ vis2(t).
// ---------------------------------------------------------------------------
extern "C" void kernel_launch(void* const* d_in, const int* in_sizes, int n_in,
                              void* d_out, int out_size)
{
    const float* v      = (const float*)d_in[0];   // [NV, T, B]
    const float* W      = (const float*)d_in[1];   // [NH, NV]
    const float* U      = (const float*)d_in[2];   // [NH, NH]
    const float* b_v    = (const float*)d_in[3];
    const float* b_h    = (const float*)d_in[4];
    const float* b_init = (const float*)d_in[5];
    float* out = (float*)d_out;

    uint32_t k0a, k0b, ksa, ksb;
    tf2x32(0u, 42u, 0u, 0u, k0a, k0b);   // k0 (t=0 step key)
    tf2x32(0u, 42u, 0u, 1u, ksa, ksb);   // ks
    static uint32_t sub[TT][4][2];
    for (int t = 0; t < TT; t++) {
        uint32_t sk0, sk1;
        if (t == 0) { sk0 = k0a; sk1 = k0b; }
        else         tf2x32(ksa, ksb, 0u, (uint32_t)(t - 1), sk0, sk1);
        for (int i = 0; i < 4; i++)
            tf2x32(sk0, sk1, 0u, (uint32_t)i, sub[t][i][0], sub[t][i][1]);
    }

    void* p;
    cudaGetSymbolAddress(&p, g_vbits);  uint32_t* pvb  = (uint32_t*)p;
    cudaGetSymbolAddress(&p, g_vmbits); uint32_t* pvmb = (uint32_t*)p;
    cudaGetSymbolAddress(&p, g_h1bits); uint32_t* ph1  = (uint32_t*)p;
    cudaGetSymbolAddress(&p, g_h2bits); uint32_t* ph2  = (uint32_t*)p;
    cudaGetSymbolAddress(&p, g_bias2);  float*    pbias= (float*)p;
    float* bias_buf[2] = { pbias, pbias + NHID * BB };

    pack_v_kernel<<<TT * NVIS * 32 / 256, 256>>>(v);

    auto mk_hid1 = [&](int t) {
        HidArgs a;
        a.W = W; a.U = U;
        a.vbits = pvb + (size_t)t * NVIS;
        a.bvec  = (t == 0) ? b_init : b_h;
        a.phase = (t == 0) ? 0 : 1;
        a.bias_rd = nullptr;
        a.bias_wr = bias_buf[t & 1];
        a.r_out = out + RT_OFF + (size_t)t * BB;
        a.s_out = nullptr;
        a.hb_out = ph1;
        a.kk0 = sub[t][0][0]; a.kk1 = sub[t][0][1];
        return a;
    };
    auto mk_hid2 = [&](int t) {
        HidArgs a;
        a.W = W; a.U = nullptr;
        a.vbits = pvmb;
        a.bvec  = nullptr;
        a.phase = 2;
        a.bias_rd = bias_buf[t & 1];
        a.bias_wr = nullptr;
        a.r_out = nullptr;
        a.s_out = out + RM_OFF + (size_t)t * BB;
        a.hb_out = ph2;
        a.kk0 = sub[t][2][0]; a.kk1 = sub[t][2][1];
        return a;
    };
    auto mk_vis1 = [&](int t) {
        VisArgs a;
        a.W = W; a.bv = b_v; a.hbits = ph1;
        a.mode = 0; a.vm_out = pvmb; a.outp = nullptr;
        a.kk0 = sub[t][1][0]; a.kk1 = sub[t][1][1];
        return a;
    };
    auto mk_vis2 = [&](int t) {
        VisArgs a;
        a.W = W; a.bv = b_v; a.hbits = ph2;
        a.mode = 1; a.vm_out = nullptr; a.outp = out + (size_t)t * BB;
        a.kk0 = sub[t][3][0]; a.kk1 = sub[t][3][1];
        return a;
    };

    // Bootstrap: hid1(0), vis1(0)
    hid_single<<<256, 64>>>(mk_hid1(0));
    vis_single<<<256, 128>>>(mk_vis1(0));

    // Pipelined steady state: independent co-resident blocks, single wave
    for (int t = 0; t < TT - 1; t++) {
        hid_fused<<<512, 64>>>(mk_hid1(t + 1), mk_hid2(t));
        vis_fused<<<512, 128>>>(mk_vis1(t + 1), mk_vis2(t));
    }

    // Tail: hid2(63), vis2(63)
    hid_single<<<256, 64>>>(mk_hid2(TT - 1));
    vis_single<<<256, 128>>>(mk_vis2(TT - 1));
}

// round 15
// speedup vs baseline: 2.0498x; 1.2960x over previous
#include <cuda_runtime.h>
#include <stdint.h>

#define NVIS 4096
#define NHID 1024
#define TT   64
#define BB   32

#define RM_OFF (NVIS*TT*BB)              /* 8388608  */
#define RT_OFF (RM_OFF + NHID*TT*BB)     /* 10485760 */

// ---------------------------------------------------------------------------
// Scratch (static device globals — no allocation). Parity-buffered for the
// 4-phase pipelined mega-kernel (concurrent writer/reader pairs).
// ---------------------------------------------------------------------------
__device__ __align__(16) uint32_t g_vbits[TT * NVIS];   // v bitmasks
__device__ __align__(16) uint32_t g_vmb[2][NVIS];       // vm bitmasks (parity t&1)
__device__ __align__(16) uint32_t g_h1b[2][NHID];       // hid1 samples (parity)
__device__ __align__(16) uint32_t g_h2b[2][NHID];       // hid2 samples (parity)
__device__ __align__(16) float    g_rT2[2][NHID * BB];  // r recurrence (parity)
__device__ __align__(16) float    g_bias4[4][NHID*BB];  // bias (t&3)

// ---------------------------------------------------------------------------
// Threefry-2x32 (exact; 20 rounds, 5 key injections) — DO NOT MODIFY (passing)
// ---------------------------------------------------------------------------
__host__ __device__ __forceinline__ void tf2x32(uint32_t k0, uint32_t k1,
                                                uint32_t x0, uint32_t x1,
                                                uint32_t& o0, uint32_t& o1) {
    uint32_t ks2 = k0 ^ k1 ^ 0x1BD11BDAu;
    x0 += k0; x1 += k1;
#define TF_R(r) { x0 += x1; x1 = (x1 << (r)) | (x1 >> (32 - (r))); x1 ^= x0; }
    TF_R(13) TF_R(15) TF_R(26) TF_R(6)   x0 += k1;  x1 += ks2 + 1u;
    TF_R(17) TF_R(29) TF_R(16) TF_R(24)  x0 += ks2; x1 += k0  + 2u;
    TF_R(13) TF_R(15) TF_R(26) TF_R(6)   x0 += k0;  x1 += k1  + 3u;
    TF_R(17) TF_R(29) TF_R(16) TF_R(24)  x0 += k1;  x1 += ks2 + 4u;
    TF_R(13) TF_R(15) TF_R(26) TF_R(6)   x0 += ks2; x1 += k0  + 5u;
#undef TF_R
    o0 = x0; o1 = x1;
}

__device__ __forceinline__ float jax_uniform(uint32_t k0, uint32_t k1, uint32_t idx) {
    uint32_t o0, o1;
    tf2x32(k0, k1, 0u, idx, o0, o1);
    uint32_t bits = o0 ^ o1;
    return __uint_as_float((bits >> 9) | 0x3f800000u) - 1.0f;
}

__device__ __forceinline__ float sigmoidf_(float x) {
    return 1.0f / (1.0f + expf(-x));
}

// ---------------------------------------------------------------------------
// Masked adds (bit-identical to fmaf(w, v, acc), v in {0,1})
// ---------------------------------------------------------------------------
__device__ __forceinline__ void madd2(float& a0, float& a1, float w0, float w1,
                                      uint32_t word, uint32_t bb) {
    asm("{\n\t.reg .pred p;\n\t.reg .b32 t;\n\t"
        "and.b32 t, %4, %5;\n\t"
        "setp.ne.u32 p, t, 0;\n\t"
        "@p add.f32 %0, %0, %2;\n\t"
        "@p add.f32 %1, %1, %3;\n\t}"
        : "+f"(a0), "+f"(a1) : "f"(w0), "f"(w1), "r"(word), "r"(bb));
}
__device__ __forceinline__ void madd4(float& a0, float& a1, float& a2, float& a3,
                                      float4 w, uint32_t word, uint32_t bb) {
    asm("{\n\t.reg .pred p;\n\t.reg .b32 t;\n\t"
        "and.b32 t, %8, %9;\n\t"
        "setp.ne.u32 p, t, 0;\n\t"
        "@p add.f32 %0, %0, %4;\n\t"
        "@p add.f32 %1, %1, %5;\n\t"
        "@p add.f32 %2, %2, %6;\n\t"
        "@p add.f32 %3, %3, %7;\n\t}"
        : "+f"(a0), "+f"(a1), "+f"(a2), "+f"(a3)
        : "f"(w.x), "f"(w.y), "f"(w.z), "f"(w.w), "r"(word), "r"(bb));
}

// ---------------------------------------------------------------------------
// cp.async helpers
// ---------------------------------------------------------------------------
__device__ __forceinline__ uint32_t smem_u32(const void* p) {
    return (uint32_t)__cvta_generic_to_shared(p);
}
__device__ __forceinline__ void cp_async16(uint32_t saddr, const void* g) {
    asm volatile("cp.async.ca.shared.global [%0], [%1], 16;\n" :: "r"(saddr), "l"(g));
}
__device__ __forceinline__ void cp_commit() {
    asm volatile("cp.async.commit_group;\n");
}
__device__ __forceinline__ void cp_wait1() {
    asm volatile("cp.async.wait_group 1;\n" ::: "memory");
}
__device__ __forceinline__ void cp_wait0() {
    asm volatile("cp.async.wait_group 0;\n" ::: "memory");
}

// Stage one [8 rows x 512 cols] float tile (16KB) into smem. 128 threads.
__device__ __forceinline__ void stage8x512_128(uint32_t sbase, const float* gsrc,
                                               int rowstride, int tid) {
#pragma unroll
    for (int q = 0; q < 8; q++) {
        int cc  = q * 128 + tid;
        int rr  = cc >> 7;
        int c16 = cc & 127;
        cp_async16(sbase + (uint32_t)(rr * 512 + c16 * 4) * 4,
                   gsrc + (size_t)rr * rowstride + c16 * 4);
    }
    cp_commit();
}

// ---------------------------------------------------------------------------
// Pack v [NV][T][B] -> bitmasks (once per replay)
// ---------------------------------------------------------------------------
__global__ void __launch_bounds__(256) pack_v_kernel(const float* __restrict__ v)
{
    int g    = blockIdx.x * 256 + threadIdx.x;
    int lane = g & 31;
    int w    = g >> 5;
    int k    = w & (NVIS - 1);
    int t    = w >> 12;
    float val = v[(size_t)k * (TT * BB) + t * BB + lane];
    uint32_t m = __ballot_sync(0xffffffffu, val != 0.0f);
    if (lane == 0) g_vbits[t * NVIS + k] = m;
}

// ---------------------------------------------------------------------------
// Args
// ---------------------------------------------------------------------------
struct HidArgs {
    const float*    W;
    const float*    U;
    const uint32_t* vbits;
    const float*    bvec;
    int             phase;     // 0: b_init, 1: U@r + b_h, 2: cached
    const float*    bias_rd;
    float*          bias_wr;
    const float*    r_rd;      // rT parity buffer read (U-pass)
    float*          r_wr;      // rT parity buffer write
    float*          r_out;     // rt column
    float*          s_out;     // r_model column
    uint32_t*       hb_out;
    uint32_t        kk0, kk1;
};
struct VisArgs {
    const float*    W;
    const float*    bv;
    const uint32_t* hbits;
    int             mode;      // 0: vm bitmask out, 1: v_model floats out
    uint32_t*       vm_out;
    float*          outp;
    uint32_t        kk0, kk1;
};

// ---------------------------------------------------------------------------
// Hidden body: 128 threads, 8 h rows per block, blk in [0,128).
// Byte-identical math to the 6.95ms build (madd2 chain, ascending k).
// ---------------------------------------------------------------------------
__device__ __forceinline__ void hid_body(int blk, const HidArgs& a, char* smraw)
{
    float (*sW)[8 * 512] = reinterpret_cast<float (*)[8 * 512]>(smraw);
    const int tid   = threadIdx.x;
    const int wid   = tid >> 5;
    const int b     = tid & 31;
    const int hbase = blk * 8;
    const int h0    = hbase + wid * 2;
    const int h1    = h0 + 1;
    const uint32_t bb  = 1u << b;
    const uint32_t sm0 = smem_u32(&sW[0][0]);
    const uint32_t sm1 = smem_u32(&sW[1][0]);

    float bias0, bias1;
    if (a.phase == 1) {
        float a0 = 0.f, a1 = 0.f;
        stage8x512_128(sm0, a.U + (size_t)hbase * NHID + 0,   NHID, tid);
        stage8x512_128(sm1, a.U + (size_t)hbase * NHID + 512, NHID, tid);
        for (int kt = 0; kt < 2; kt++) {
            if (kt == 0) cp_wait1(); else cp_wait0();
            __syncthreads();
            const float* w0p = &sW[kt][(wid * 2 + 0) * 512];
            const float* w1p = &sW[kt][(wid * 2 + 1) * 512];
            const float* rp  = a.r_rd + (size_t)(kt * 512) * 32 + b;
#pragma unroll 4
            for (int k = 0; k < 512; k += 4) {
                float4 w0 = *reinterpret_cast<const float4*>(w0p + k);
                float4 w1 = *reinterpret_cast<const float4*>(w1p + k);
                float r0 = rp[(k + 0) * 32];
                float r1 = rp[(k + 1) * 32];
                float r2 = rp[(k + 2) * 32];
                float r3 = rp[(k + 3) * 32];
                a0 = fmaf(w0.x, r0, a0); a1 = fmaf(w1.x, r0, a1);
                a0 = fmaf(w0.y, r1, a0); a1 = fmaf(w1.y, r1, a1);
                a0 = fmaf(w0.z, r2, a0); a1 = fmaf(w1.z, r2, a1);
                a0 = fmaf(w0.w, r3, a0); a1 = fmaf(w1.w, r3, a1);
            }
            __syncthreads();
        }
        bias0 = a0 + a.bvec[h0];
        bias1 = a1 + a.bvec[h1];
        a.bias_wr[h0 * 32 + b] = bias0;
        a.bias_wr[h1 * 32 + b] = bias1;
    } else if (a.phase == 0) {
        bias0 = a.bvec[h0];
        bias1 = a.bvec[h1];
        a.bias_wr[h0 * 32 + b] = bias0;
        a.bias_wr[h1 * 32 + b] = bias1;
    } else {
        bias0 = a.bias_rd[h0 * 32 + b];
        bias1 = a.bias_rd[h1 * 32 + b];
    }

    float a0 = 0.f, a1 = 0.f;
    stage8x512_128(sm0, a.W + (size_t)hbase * NVIS + 0,   NVIS, tid);
    stage8x512_128(sm1, a.W + (size_t)hbase * NVIS + 512, NVIS, tid);
    for (int kt = 0; kt < 8; kt++) {
        if (kt < 7) cp_wait1(); else cp_wait0();
        __syncthreads();
        const float* w0p = &sW[kt & 1][(wid * 2 + 0) * 512];
        const float* w1p = &sW[kt & 1][(wid * 2 + 1) * 512];
        const uint32_t* vb = a.vbits + kt * 512;
#pragma unroll 8
        for (int k = 0; k < 512; k += 4) {
            uint4 vw = *reinterpret_cast<const uint4*>(vb + k);
            float4 w0 = *reinterpret_cast<const float4*>(w0p + k);
            float4 w1 = *reinterpret_cast<const float4*>(w1p + k);
            madd2(a0, a1, w0.x, w1.x, vw.x, bb);
            madd2(a0, a1, w0.y, w1.y, vw.y, bb);
            madd2(a0, a1, w0.z, w1.z, vw.z, bb);
            madd2(a0, a1, w0.w, w1.w, vw.w, bb);
        }
        __syncthreads();
        if (kt + 2 < 8)
            stage8x512_128((kt & 1) ? sm1 : sm0,
                           a.W + (size_t)hbase * NVIS + (kt + 2) * 512, NVIS, tid);
    }

    float r0 = sigmoidf_(a0 + bias0);
    float r1 = sigmoidf_(a1 + bias1);

    if (a.phase != 2) {
        a.r_out[h0 * (TT * BB) + b] = r0;
        a.r_out[h1 * (TT * BB) + b] = r1;
        a.r_wr[h0 * 32 + b] = r0;
        a.r_wr[h1 * 32 + b] = r1;
    }
    float u0 = jax_uniform(a.kk0, a.kk1, (uint32_t)(h0 * BB + b));
    float u1 = jax_uniform(a.kk0, a.kk1, (uint32_t)(h1 * BB + b));
    int p0 = (u0 < r0), p1 = (u1 < r1);
    uint32_t m0 = __ballot_sync(0xffffffffu, p0);
    uint32_t m1 = __ballot_sync(0xffffffffu, p1);
    if (b == 0) { a.hb_out[h0] = m0; a.hb_out[h1] = m1; }
    if (a.phase == 2) {
        a.s_out[h0 * (TT * BB) + b] = p0 ? 1.0f : 0.0f;
        a.s_out[h1 * (TT * BB) + b] = p1 ? 1.0f : 0.0f;
    }
}

// ---------------------------------------------------------------------------
// Visible body: 128 threads, 16 i per block, blk in [0,256).
// Byte-identical math to the 6.95ms build (madd4 chain, ascending j).
// ---------------------------------------------------------------------------
__device__ __forceinline__ void vis_body(int blk, const VisArgs& a, char* smraw)
{
    float (*sW)[256 * 16] = reinterpret_cast<float (*)[256 * 16]>(smraw);
    const int tid   = threadIdx.x;
    const int wid   = tid >> 5;
    const int b     = tid & 31;
    const int ibase = blk * 16;
    const int i0    = ibase + wid * 4;
    const uint32_t bb  = 1u << b;
    const uint32_t sm0 = smem_u32(&sW[0][0]);
    const uint32_t sm1 = smem_u32(&sW[1][0]);

    auto stage = [&](uint32_t sbase, int jt) {
#pragma unroll
        for (int q = 0; q < 8; q++) {
            int cc  = q * 128 + tid;
            int rr  = cc >> 2;
            int c16 = cc & 3;
            cp_async16(sbase + (uint32_t)(rr * 16 + c16 * 4) * 4,
                       a.W + (size_t)(jt * 256 + rr) * NVIS + ibase + c16 * 4);
        }
        cp_commit();
    };

    float a0 = 0.f, a1 = 0.f, a2 = 0.f, a3 = 0.f;
    stage(sm0, 0);
    stage(sm1, 1);
    for (int jt = 0; jt < 4; jt++) {
        if (jt < 3) cp_wait1(); else cp_wait0();
        __syncthreads();
        const float* wp = &sW[jt & 1][wid * 4];
        const uint32_t* hb = a.hbits + jt * 256;
#pragma unroll 4
        for (int j = 0; j < 256; j += 4) {
            uint4 hw = *reinterpret_cast<const uint4*>(hb + j);
            float4 w;
            w = *reinterpret_cast<const float4*>(wp + (j + 0) * 16);
            madd4(a0, a1, a2, a3, w, hw.x, bb);
            w = *reinterpret_cast<const float4*>(wp + (j + 1) * 16);
            madd4(a0, a1, a2, a3, w, hw.y, bb);
            w = *reinterpret_cast<const float4*>(wp + (j + 2) * 16);
            madd4(a0, a1, a2, a3, w, hw.z, bb);
            w = *reinterpret_cast<const float4*>(wp + (j + 3) * 16);
            madd4(a0, a1, a2, a3, w, hw.w, bb);
        }
        __syncthreads();
        if (jt + 2 < 4) stage((jt & 1) ? sm1 : sm0, jt + 2);
    }

    float accs[4] = {a0, a1, a2, a3};
#pragma unroll
    for (int q = 0; q < 4; q++) {
        float r = sigmoidf_(accs[q] + a.bv[i0 + q]);
        float u = jax_uniform(a.kk0, a.kk1, (uint32_t)((i0 + q) * BB + b));
        int pr = (u < r);
        uint32_t m = __ballot_sync(0xffffffffu, pr);
        if (a.mode == 0) {
            if (b == 0) a.vm_out[i0 + q] = m;
        } else {
            a.outp[(size_t)(i0 + q) * (TT * BB) + b] = pr ? 1.0f : 0.0f;
        }
    }
}

// ---------------------------------------------------------------------------
// MEGA slot kernel: 768 blocks x 128 threads, four independent phases.
// [0,128) hid1(s+1) | [128,256) hid2(s-1) | [256,512) vis1(s) | [512,768) vis2(s-2)
// ---------------------------------------------------------------------------
__global__ void __launch_bounds__(128, 5) mega_kernel(
    HidArgs h1, int e_h1, HidArgs h2, int e_h2,
    VisArgs v1, int e_v1, VisArgs v2, int e_v2)
{
    __shared__ __align__(16) char smraw[32768];
    int bx = blockIdx.x;
    if (bx < 128) {
        if (e_h1) hid_body(bx, h1, smraw);
    } else if (bx < 256) {
        if (e_h2) hid_body(bx - 128, h2, smraw);
    } else if (bx < 512) {
        if (e_v1) vis_body(bx - 256, v1, smraw);
    } else {
        if (e_v2) vis_body(bx - 512, v2, smraw);
    }
}

// ---------------------------------------------------------------------------
// Host: partitionable-threefry key schedule + 4-deep software pipeline.
// Slot s runs {hid1(s+1), vis1(s), hid2(s-1), vis2(s-2)} — all independent.
// ---------------------------------------------------------------------------
extern "C" void kernel_launch(void* const* d_in, const int* in_sizes, int n_in,
                              void* d_out, int out_size)
{
    const float* v      = (const float*)d_in[0];   // [NV, T, B]
    const float* W      = (const float*)d_in[1];   // [NH, NV]
    const float* U      = (const float*)d_in[2];   // [NH, NH]
    const float* b_v    = (const float*)d_in[3];
    const float* b_h    = (const float*)d_in[4];
    const float* b_init = (const float*)d_in[5];
    float* out = (float*)d_out;

    uint32_t k0a, k0b, ksa, ksb;
    tf2x32(0u, 42u, 0u, 0u, k0a, k0b);   // k0 (t=0 step key)
    tf2x32(0u, 42u, 0u, 1u, ksa, ksb);   // ks
    static uint32_t sub[TT][4][2];
    for (int t = 0; t < TT; t++) {
        uint32_t sk0, sk1;
        if (t == 0) { sk0 = k0a; sk1 = k0b; }
        else         tf2x32(ksa, ksb, 0u, (uint32_t)(t - 1), sk0, sk1);
        for (int i = 0; i < 4; i++)
            tf2x32(sk0, sk1, 0u, (uint32_t)i, sub[t][i][0], sub[t][i][1]);
    }

    void* p;
    cudaGetSymbolAddress(&p, g_vbits); uint32_t* pvb = (uint32_t*)p;
    cudaGetSymbolAddress(&p, g_vmb);   uint32_t* pvm = (uint32_t*)p;
    cudaGetSymbolAddress(&p, g_h1b);   uint32_t* ph1 = (uint32_t*)p;
    cudaGetSymbolAddress(&p, g_h2b);   uint32_t* ph2 = (uint32_t*)p;
    cudaGetSymbolAddress(&p, g_rT2);   float*    prT = (float*)p;
    cudaGetSymbolAddress(&p, g_bias4); float*    pbi = (float*)p;

    auto vmb  = [&](int par) { return pvm + (size_t)par * NVIS; };
    auto h1b  = [&](int par) { return ph1 + (size_t)par * NHID; };
    auto h2b  = [&](int par) { return ph2 + (size_t)par * NHID; };
    auto rTb  = [&](int par) { return prT + (size_t)par * NHID * BB; };
    auto bib  = [&](int q)   { return pbi + (size_t)q * NHID * BB; };

    pack_v_kernel<<<TT * NVIS * 32 / 256, 256>>>(v);

    auto mk_hid1 = [&](int t) {
        HidArgs a;
        a.W = W; a.U = U;
        a.vbits = pvb + (size_t)t * NVIS;
        a.bvec  = (t == 0) ? b_init : b_h;
        a.phase = (t == 0) ? 0 : 1;
        a.bias_rd = nullptr;
        a.bias_wr = bib(t & 3);
        a.r_rd  = rTb((t + 1) & 1);      // r(t-1) buffer
        a.r_wr  = rTb(t & 1);            // r(t) buffer
        a.r_out = out + RT_OFF + (size_t)t * BB;
        a.s_out = nullptr;
        a.hb_out = h1b(t & 1);
        a.kk0 = sub[t][0][0]; a.kk1 = sub[t][0][1];
        return a;
    };
    auto mk_hid2 = [&](int t) {
        HidArgs a;
        a.W = W; a.U = nullptr;
        a.vbits = vmb(t & 1);
        a.bvec  = nullptr;
        a.phase = 2;
        a.bias_rd = bib(t & 3);
        a.bias_wr = nullptr;
        a.r_rd = nullptr; a.r_wr = nullptr;
        a.r_out = nullptr;
        a.s_out = out + RM_OFF + (size_t)t * BB;
        a.hb_out = h2b(t & 1);
        a.kk0 = sub[t][2][0]; a.kk1 = sub[t][2][1];
        return a;
    };
    auto mk_vis1 = [&](int t) {
        VisArgs a;
        a.W = W; a.bv = b_v; a.hbits = h1b(t & 1);
        a.mode = 0; a.vm_out = vmb(t & 1); a.outp = nullptr;
        a.kk0 = sub[t][1][0]; a.kk1 = sub[t][1][1];
        return a;
    };
    auto mk_vis2 = [&](int t) {
        VisArgs a;
        a.W = W; a.bv = b_v; a.hbits = h2b(t & 1);
        a.mode = 1; a.vm_out = nullptr; a.outp = out + (size_t)t * BB;
        a.kk0 = sub[t][3][0]; a.kk1 = sub[t][3][1];
        return a;
    };

    HidArgs hz = {};
    VisArgs vz = {};

    for (int s = -1; s <= TT + 1; s++) {
        int t_h1 = s + 1, t_v1 = s, t_h2 = s - 1, t_v2 = s - 2;
        int e_h1 = (t_h1 >= 0 && t_h1 < TT);
        int e_v1 = (t_v1 >= 0 && t_v1 < TT);
        int e_h2 = (t_h2 >= 0 && t_h2 < TT);
        int e_v2 = (t_v2 >= 0 && t_v2 < TT);
        HidArgs a1 = e_h1 ? mk_hid1(t_h1) : hz;
        HidArgs a2 = e_h2 ? mk_hid2(t_h2) : hz;
        VisArgs b1 = e_v1 ? mk_vis1(t_v1) : vz;
        VisArgs b2 = e_v2 ? mk_vis2(t_v2) : vz;
        mega_kernel<<<768, 128>>>(a1, e_h1, a2, e_h2, b1, e_v1, b2, e_v2);
    }
}